// round 2
// baseline (speedup 1.0000x reference)
#include <cuda_runtime.h>
#include <math.h>

#define N_NODES 20000
#define N_EDGES 320000
#define DMAX    512

// ---------------- scratch (static device globals; no allocation allowed) ----
__device__ __align__(16) float g_xl[N_NODES * DMAX];
__device__ __align__(16) float g_xr[N_NODES * DMAX];
__device__ __align__(16) float g_sk[N_NODES * DMAX];
__device__ __align__(16) float g_h1[N_NODES * 512];
__device__ __align__(16) float g_h2[N_NODES * 256];
__device__ float g_score[N_EDGES];
__device__ float g_alpha[N_EDGES];
__device__ int   g_eid  [N_EDGES];
__device__ int   g_srcs [N_EDGES];
__device__ int   g_count [N_NODES];
__device__ int   g_cursor[N_NODES];
__device__ int   g_rowptr[N_NODES + 1];

// ---------------- CSR build (counting sort by dst) --------------------------
__global__ void zero_counts_kernel() {
    int i = blockIdx.x * blockDim.x + threadIdx.x;
    if (i < N_NODES) { g_count[i] = 0; g_cursor[i] = 0; }
}

__global__ void hist_kernel(const int* __restrict__ dst) {
    int e = blockIdx.x * blockDim.x + threadIdx.x;
    if (e < N_EDGES) atomicAdd(&g_count[dst[e]], 1);
}

__global__ void scan_kernel() {
    __shared__ int part[256];
    const int n = N_NODES;
    int tid = threadIdx.x;
    int chunk = (n + 255) / 256;
    int beg = tid * chunk;
    int end = min(beg + chunk, n);
    int sum = 0;
    for (int i = beg; i < end; i++) sum += g_count[i];
    part[tid] = sum;
    __syncthreads();
    // Hillis-Steele inclusive scan over 256 partials
    for (int off = 1; off < 256; off <<= 1) {
        int v = (tid >= off) ? part[tid - off] : 0;
        __syncthreads();
        part[tid] += v;
        __syncthreads();
    }
    int run = (tid > 0) ? part[tid - 1] : 0;
    for (int i = beg; i < end; i++) {
        int c = g_count[i];
        g_rowptr[i] = run;
        run += c;
    }
    if (tid == 255) g_rowptr[n] = run;
}

__global__ void scatter_kernel(const int* __restrict__ src, const int* __restrict__ dst) {
    int e = blockIdx.x * blockDim.x + threadIdx.x;
    if (e < N_EDGES) {
        int d = dst[e];
        int pos = g_rowptr[d] + atomicAdd(&g_cursor[d], 1);
        g_eid[pos]  = e;
        g_srcs[pos] = src[e];
    }
}

// ---------------- fp32 tiled GEMM: C[M,N] = A[M,K] * B[K,N] -----------------
// BM=64, BN=64, BK=16, 256 threads, 4x4 register tile per thread.
// Requires: K % 16 == 0, N % 64 == 0 (true here: K in {256,512}, N in {512,256,128}).
__global__ void gemm64_kernel(const float* __restrict__ A, const float* __restrict__ B,
                              float* __restrict__ C, int M, int N, int K) {
    __shared__ float As[16][64];
    __shared__ float Bs[16][64];
    int tid = threadIdx.x;
    int blockRow = blockIdx.y * 64;
    int blockCol = blockIdx.x * 64;
    int ty = tid / 16, tx = tid % 16;

    int aRow = tid / 4;          // 0..63
    int aCol = (tid % 4) * 4;    // 0,4,8,12
    int bRow = tid / 16;         // 0..15
    int bCol = (tid % 16) * 4;   // 0..60

    float acc[4][4];
#pragma unroll
    for (int i = 0; i < 4; i++)
#pragma unroll
        for (int j = 0; j < 4; j++) acc[i][j] = 0.f;

    for (int k0 = 0; k0 < K; k0 += 16) {
        int gRow = blockRow + aRow;
        float4 va = make_float4(0.f, 0.f, 0.f, 0.f);
        if (gRow < M)
            va = *(const float4*)(A + (size_t)gRow * K + k0 + aCol);
        As[aCol + 0][aRow] = va.x;
        As[aCol + 1][aRow] = va.y;
        As[aCol + 2][aRow] = va.z;
        As[aCol + 3][aRow] = va.w;

        float4 vb = *(const float4*)(B + (size_t)(k0 + bRow) * N + blockCol + bCol);
        *(float4*)&Bs[bRow][bCol] = vb;
        __syncthreads();

#pragma unroll
        for (int k = 0; k < 16; k++) {
            float ra[4], rb[4];
#pragma unroll
            for (int i = 0; i < 4; i++) ra[i] = As[k][ty * 4 + i];
#pragma unroll
            for (int j = 0; j < 4; j++) rb[j] = Bs[k][tx * 4 + j];
#pragma unroll
            for (int i = 0; i < 4; i++)
#pragma unroll
                for (int j = 0; j < 4; j++) acc[i][j] = fmaf(ra[i], rb[j], acc[i][j]);
        }
        __syncthreads();
    }

#pragma unroll
    for (int i = 0; i < 4; i++) {
        int r = blockRow + ty * 4 + i;
        if (r < M) {
            float* crow = C + (size_t)r * N + blockCol + tx * 4;
            float4 v = make_float4(acc[i][0], acc[i][1], acc[i][2], acc[i][3]);
            *(float4*)crow = v;
        }
    }
}

// ---------------- edge attention scores: warp per edge ----------------------
__global__ void scores_kernel(const float* __restrict__ xl, const float* __restrict__ xr,
                              const float* __restrict__ att,
                              const int* __restrict__ src, const int* __restrict__ dst,
                              int D) {
    int warp = (blockIdx.x * blockDim.x + threadIdx.x) >> 5;
    if (warp >= N_EDGES) return;
    int lane = threadIdx.x & 31;
    int s = src[warp], d = dst[warp];
    const float4* a = (const float4*)(xl + (size_t)s * D);
    const float4* b = (const float4*)(xr + (size_t)d * D);
    const float4* w = (const float4*)att;
    int D4 = D >> 2;
    float acc = 0.f;
    for (int i = lane; i < D4; i += 32) {
        float4 va = a[i], vb = b[i], vw = w[i];
        float t;
        t = va.x + vb.x; acc = fmaf((t > 0.f ? t : 0.2f * t), vw.x, acc);
        t = va.y + vb.y; acc = fmaf((t > 0.f ? t : 0.2f * t), vw.y, acc);
        t = va.z + vb.z; acc = fmaf((t > 0.f ? t : 0.2f * t), vw.z, acc);
        t = va.w + vb.w; acc = fmaf((t > 0.f ? t : 0.2f * t), vw.w, acc);
    }
#pragma unroll
    for (int off = 16; off > 0; off >>= 1)
        acc += __shfl_xor_sync(0xFFFFFFFFu, acc, off);
    if (lane == 0) g_score[warp] = acc;
}

// ---------------- segment softmax: warp per dst node ------------------------
__global__ void softmax_kernel() {
    int v = (blockIdx.x * blockDim.x + threadIdx.x) >> 5;
    if (v >= N_NODES) return;
    int lane = threadIdx.x & 31;
    int beg = g_rowptr[v], end = g_rowptr[v + 1];
    if (beg == end) return;

    float m = -INFINITY;
    for (int i = beg + lane; i < end; i += 32)
        m = fmaxf(m, g_score[g_eid[i]]);
#pragma unroll
    for (int off = 16; off > 0; off >>= 1)
        m = fmaxf(m, __shfl_xor_sync(0xFFFFFFFFu, m, off));

    float s = 0.f;
    for (int i = beg + lane; i < end; i += 32) {
        float ex = __expf(g_score[g_eid[i]] - m);
        g_alpha[i] = ex;
        s += ex;
    }
#pragma unroll
    for (int off = 16; off > 0; off >>= 1)
        s += __shfl_xor_sync(0xFFFFFFFFu, s, off);
    float inv = 1.f / (s + 1e-16f);
    for (int i = beg + lane; i < end; i += 32)
        g_alpha[i] *= inv;
}

// ---------------- aggregation: block (128 thr) per dst node -----------------
// out[v] = sum_e alpha_e * xl[src_e] + bc + bs + skip[v];  optional relu
__global__ void aggregate_kernel(const float* __restrict__ xl, const float* __restrict__ sk,
                                 const float* __restrict__ bc, const float* __restrict__ bs,
                                 float* __restrict__ out, int D, int doRelu) {
    int v = blockIdx.x;
    int tid = threadIdx.x;
    int beg = g_rowptr[v], end = g_rowptr[v + 1];
    __shared__ int   s_src[128];
    __shared__ float s_a[128];

    int npt = D >> 7;  // 4, 2 or 1
    float acc[4] = {0.f, 0.f, 0.f, 0.f};

    for (int c = beg; c < end; c += 128) {
        int m = min(128, end - c);
        if (tid < m) {
            s_src[tid] = g_srcs[c + tid];
            s_a[tid]   = g_alpha[c + tid];
        }
        __syncthreads();
        for (int j = 0; j < m; j++) {
            const float* row = xl + (size_t)s_src[j] * D;
            float a = s_a[j];
#pragma unroll
            for (int t = 0; t < 4; t++)
                if (t < npt) acc[t] = fmaf(a, row[tid + t * 128], acc[t]);
        }
        __syncthreads();
    }

#pragma unroll
    for (int t = 0; t < 4; t++) {
        if (t < npt) {
            int d = tid + t * 128;
            float o = acc[t] + bc[d] + bs[d] + sk[(size_t)v * D + d];
            if (doRelu) o = fmaxf(o, 0.f);
            out[(size_t)v * D + d] = o;
        }
    }
}

// ---------------- host-side orchestration -----------------------------------
static void run_layer(const float* A, int K, int D,
                      const float* Wl, const float* Wr, const float* Ws,
                      const float* att, const float* bc, const float* bs,
                      float* out, int doRelu,
                      float* xl, float* xr, float* sk,
                      const int* src, const int* dst) {
    dim3 gg((D + 63) / 64, (N_NODES + 63) / 64);
    gemm64_kernel<<<gg, 256>>>(A, Wl, xl, N_NODES, D, K);
    gemm64_kernel<<<gg, 256>>>(A, Wr, xr, N_NODES, D, K);
    gemm64_kernel<<<gg, 256>>>(A, Ws, sk, N_NODES, D, K);

    int warpsPerBlock = 8;
    int nb = (N_EDGES + warpsPerBlock - 1) / warpsPerBlock;
    scores_kernel<<<nb, warpsPerBlock * 32>>>(xl, xr, att, src, dst, D);

    int nbv = (N_NODES + warpsPerBlock - 1) / warpsPerBlock;
    softmax_kernel<<<nbv, warpsPerBlock * 32>>>();

    aggregate_kernel<<<N_NODES, 128>>>(xl, sk, bc, bs, out, D, doRelu);
}

extern "C" void kernel_launch(void* const* d_in, const int* in_sizes, int n_in,
                              void* d_out, int out_size) {
    const float* x  = (const float*)d_in[0];
    const int*   ei = (const int*)d_in[1];
    const int* src = ei;
    const int* dst = ei + N_EDGES;

    const float* Wl[3]  = {(const float*)d_in[2],  (const float*)d_in[8],  (const float*)d_in[14]};
    const float* Wr[3]  = {(const float*)d_in[3],  (const float*)d_in[9],  (const float*)d_in[15]};
    const float* att[3] = {(const float*)d_in[4],  (const float*)d_in[10], (const float*)d_in[16]};
    const float* bc[3]  = {(const float*)d_in[5],  (const float*)d_in[11], (const float*)d_in[17]};
    const float* Ws[3]  = {(const float*)d_in[6],  (const float*)d_in[12], (const float*)d_in[18]};
    const float* bs[3]  = {(const float*)d_in[7],  (const float*)d_in[13], (const float*)d_in[19]};

    float *xl, *xr, *sk, *h1, *h2;
    cudaGetSymbolAddress((void**)&xl, g_xl);
    cudaGetSymbolAddress((void**)&xr, g_xr);
    cudaGetSymbolAddress((void**)&sk, g_sk);
    cudaGetSymbolAddress((void**)&h1, g_h1);
    cudaGetSymbolAddress((void**)&h2, g_h2);

    // CSR build (counting sort of edges by dst)
    zero_counts_kernel<<<(N_NODES + 255) / 256, 256>>>();
    hist_kernel<<<(N_EDGES + 255) / 256, 256>>>(dst);
    scan_kernel<<<1, 256>>>();
    scatter_kernel<<<(N_EDGES + 255) / 256, 256>>>(src, dst);

    // Layer 1: 256 -> 512, relu
    run_layer(x,  256, 512, Wl[0], Wr[0], Ws[0], att[0], bc[0], bs[0], h1, 1, xl, xr, sk, src, dst);
    // Layer 2: 512 -> 256, relu
    run_layer(h1, 512, 256, Wl[1], Wr[1], Ws[1], att[1], bc[1], bs[1], h2, 1, xl, xr, sk, src, dst);
    // Layer 3: 256 -> 128, no relu
    run_layer(h2, 256, 128, Wl[2], Wr[2], Ws[2], att[2], bc[2], bs[2], (float*)d_out, 0, xl, xr, sk, src, dst);
}

// round 4
// speedup vs baseline: 1.8795x; 1.8795x over previous
#include <cuda_runtime.h>
#include <cstdint>
#include <stdint.h>
#include <math.h>

#define N_NODES 20000
#define N_EDGES 320000
#define DMAX    512

// ---------------- scratch (static device globals; no allocation allowed) ----
__device__ __align__(16) float g_xl[N_NODES * DMAX];
__device__ __align__(16) float g_xr[N_NODES * DMAX];
__device__ __align__(16) float g_sk[N_NODES * DMAX];
__device__ __align__(16) float g_h1[N_NODES * 512];
__device__ __align__(16) float g_h2[N_NODES * 256];
__device__ float g_score[N_EDGES];
__device__ float g_alpha[N_EDGES];
__device__ int   g_eid  [N_EDGES];
__device__ int   g_srcs [N_EDGES];
__device__ int   g_count [N_NODES];
__device__ int   g_cursor[N_NODES];
__device__ int   g_rowptr[N_NODES + 1];

// ---------------- CSR build (counting sort by dst) --------------------------
__global__ void zero_counts_kernel() {
    int i = blockIdx.x * blockDim.x + threadIdx.x;
    if (i < N_NODES) { g_count[i] = 0; g_cursor[i] = 0; }
}

__global__ void hist_kernel(const int* __restrict__ dst) {
    int e = blockIdx.x * blockDim.x + threadIdx.x;
    if (e < N_EDGES) atomicAdd(&g_count[dst[e]], 1);
}

__global__ void scan_kernel() {
    __shared__ int part[256];
    const int n = N_NODES;
    int tid = threadIdx.x;
    int chunk = (n + 255) / 256;
    int beg = tid * chunk;
    int end = min(beg + chunk, n);
    int sum = 0;
    for (int i = beg; i < end; i++) sum += g_count[i];
    part[tid] = sum;
    __syncthreads();
    for (int off = 1; off < 256; off <<= 1) {
        int v = (tid >= off) ? part[tid - off] : 0;
        __syncthreads();
        part[tid] += v;
        __syncthreads();
    }
    int run = (tid > 0) ? part[tid - 1] : 0;
    for (int i = beg; i < end; i++) {
        int c = g_count[i];
        g_rowptr[i] = run;
        run += c;
    }
    if (tid == 255) g_rowptr[n] = run;
}

__global__ void scatter_kernel(const int* __restrict__ src, const int* __restrict__ dst) {
    int e = blockIdx.x * blockDim.x + threadIdx.x;
    if (e < N_EDGES) {
        int d = dst[e];
        int pos = g_rowptr[d] + atomicAdd(&g_cursor[d], 1);
        g_eid[pos]  = e;
        g_srcs[pos] = src[e];
    }
}

// ---------------- TF32 tensor-core GEMM: C[M,N] = A[M,K] * B[K,N] -----------
// CTA tile 128x128x16, 8 warps (4m x 2n), warp tile 32x64, mma.m16n8k8 tf32.
// 2-stage cp.async pipeline. Requires K%16==0, N%128==0.
#define BM 128
#define BN 128
#define BK 16
#define AP (BK + 4)    // As row stride (floats): conflict-free frag loads
#define BP (BN + 8)    // Bs row stride (floats): conflict-free frag loads

__device__ __forceinline__ uint32_t f2tf32(float x) {
    uint32_t r;
    asm("cvt.rna.tf32.f32 %0, %1;" : "=r"(r) : "f"(x));
    return r;
}

__device__ __forceinline__ void cpasync16(void* smem, const void* g, int sz) {
    uint32_t sa = (uint32_t)__cvta_generic_to_shared(smem);
    asm volatile("cp.async.cg.shared.global [%0], [%1], 16, %2;\n"
                 :: "r"(sa), "l"(g), "r"(sz));
}

__global__ __launch_bounds__(256, 2)
void gemm_tf32_kernel(const float* __restrict__ A, const float* __restrict__ B,
                      float* __restrict__ C, int M, int N, int K) {
    __shared__ float As[2][BM][AP];
    __shared__ float Bs[2][BK][BP];

    int tid  = threadIdx.x;
    int warp = tid >> 5;
    int lane = tid & 31;
    int blockRow = blockIdx.y * BM;
    int blockCol = blockIdx.x * BN;
    int wm = (warp >> 1) * 32;   // warp m offset within CTA tile
    int wn = (warp & 1) * 64;    // warp n offset

    float acc[2][8][4];
#pragma unroll
    for (int i = 0; i < 2; i++)
#pragma unroll
        for (int j = 0; j < 8; j++)
#pragma unroll
            for (int t = 0; t < 4; t++) acc[i][j][t] = 0.f;

    // ---- stage loader: A chunks (128r x 4 float4), B chunks (16r x 32 float4)
    auto loadStage = [&](int s, int k0) {
#pragma unroll
        for (int j = 0; j < 2; j++) {
            int c = tid + j * 256;
            int row = c >> 2;
            int col = (c & 3) * 4;
            int gRow = blockRow + row;
            int ok = (gRow < M);
            const float* gp = A + (size_t)(ok ? gRow : 0) * K + k0 + col;
            cpasync16(&As[s][row][col], gp, ok ? 16 : 0);
        }
#pragma unroll
        for (int j = 0; j < 2; j++) {
            int c = tid + j * 256;
            int k = c >> 5;
            int col = (c & 31) * 4;
            const float* gp = B + (size_t)(k0 + k) * N + blockCol + col;
            cpasync16(&Bs[s][k][col], gp, 16);
        }
        asm volatile("cp.async.commit_group;\n");
    };

    int nK = K / BK;
    loadStage(0, 0);

    for (int kt = 0; kt < nK; kt++) {
        int s = kt & 1;
        if (kt + 1 < nK) {
            loadStage(s ^ 1, (kt + 1) * BK);
            asm volatile("cp.async.wait_group 1;\n");
        } else {
            asm volatile("cp.async.wait_group 0;\n");
        }
        __syncthreads();

#pragma unroll
        for (int ks = 0; ks < 2; ks++) {
            int kb = ks * 8;
            uint32_t aF[2][4];
#pragma unroll
            for (int i = 0; i < 2; i++) {
                int r0 = wm + i * 16 + (lane >> 2);
                int c0 = kb + (lane & 3);
                aF[i][0] = f2tf32(As[s][r0][c0]);
                aF[i][1] = f2tf32(As[s][r0 + 8][c0]);
                aF[i][2] = f2tf32(As[s][r0][c0 + 4]);
                aF[i][3] = f2tf32(As[s][r0 + 8][c0 + 4]);
            }
            uint32_t bF[8][2];
#pragma unroll
            for (int j = 0; j < 8; j++) {
                int kr = kb + (lane & 3);
                int nc = wn + j * 8 + (lane >> 2);
                bF[j][0] = f2tf32(Bs[s][kr][nc]);
                bF[j][1] = f2tf32(Bs[s][kr + 4][nc]);
            }
#pragma unroll
            for (int i = 0; i < 2; i++)
#pragma unroll
                for (int j = 0; j < 8; j++) {
                    asm volatile(
                        "mma.sync.aligned.m16n8k8.row.col.f32.tf32.tf32.f32 "
                        "{%0,%1,%2,%3}, {%4,%5,%6,%7}, {%8,%9}, {%0,%1,%2,%3};\n"
                        : "+f"(acc[i][j][0]), "+f"(acc[i][j][1]),
                          "+f"(acc[i][j][2]), "+f"(acc[i][j][3])
                        : "r"(aF[i][0]), "r"(aF[i][1]), "r"(aF[i][2]), "r"(aF[i][3]),
                          "r"(bF[j][0]), "r"(bF[j][1]));
                }
        }
        __syncthreads();
    }

    // ---- epilogue
#pragma unroll
    for (int i = 0; i < 2; i++) {
#pragma unroll
        for (int j = 0; j < 8; j++) {
            int r0 = blockRow + wm + i * 16 + (lane >> 2);
            int c0 = blockCol + wn + j * 8 + (lane & 3) * 2;
            if (r0 < M) {
                float2 v = make_float2(acc[i][j][0], acc[i][j][1]);
                *(float2*)(C + (size_t)r0 * N + c0) = v;
            }
            if (r0 + 8 < M) {
                float2 v = make_float2(acc[i][j][2], acc[i][j][3]);
                *(float2*)(C + (size_t)(r0 + 8) * N + c0) = v;
            }
        }
    }
}

// ---------------- edge attention scores: warp per edge ----------------------
__global__ void scores_kernel(const float* __restrict__ xl, const float* __restrict__ xr,
                              const float* __restrict__ att,
                              const int* __restrict__ src, const int* __restrict__ dst,
                              int D) {
    int warp = (blockIdx.x * blockDim.x + threadIdx.x) >> 5;
    if (warp >= N_EDGES) return;
    int lane = threadIdx.x & 31;
    int s = src[warp], d = dst[warp];
    const float4* a = (const float4*)(xl + (size_t)s * D);
    const float4* b = (const float4*)(xr + (size_t)d * D);
    const float4* w = (const float4*)att;
    int D4 = D >> 2;
    float acc = 0.f;
    for (int i = lane; i < D4; i += 32) {
        float4 va = a[i], vb = b[i], vw = w[i];
        float t;
        t = va.x + vb.x; acc = fmaf((t > 0.f ? t : 0.2f * t), vw.x, acc);
        t = va.y + vb.y; acc = fmaf((t > 0.f ? t : 0.2f * t), vw.y, acc);
        t = va.z + vb.z; acc = fmaf((t > 0.f ? t : 0.2f * t), vw.z, acc);
        t = va.w + vb.w; acc = fmaf((t > 0.f ? t : 0.2f * t), vw.w, acc);
    }
#pragma unroll
    for (int off = 16; off > 0; off >>= 1)
        acc += __shfl_xor_sync(0xFFFFFFFFu, acc, off);
    if (lane == 0) g_score[warp] = acc;
}

// ---------------- segment softmax: warp per dst node ------------------------
__global__ void softmax_kernel() {
    int v = (blockIdx.x * blockDim.x + threadIdx.x) >> 5;
    if (v >= N_NODES) return;
    int lane = threadIdx.x & 31;
    int beg = g_rowptr[v], end = g_rowptr[v + 1];
    if (beg == end) return;

    float m = -INFINITY;
    for (int i = beg + lane; i < end; i += 32)
        m = fmaxf(m, g_score[g_eid[i]]);
#pragma unroll
    for (int off = 16; off > 0; off >>= 1)
        m = fmaxf(m, __shfl_xor_sync(0xFFFFFFFFu, m, off));

    float s = 0.f;
    for (int i = beg + lane; i < end; i += 32) {
        float ex = __expf(g_score[g_eid[i]] - m);
        g_alpha[i] = ex;
        s += ex;
    }
#pragma unroll
    for (int off = 16; off > 0; off >>= 1)
        s += __shfl_xor_sync(0xFFFFFFFFu, s, off);
    float inv = 1.f / (s + 1e-16f);
    for (int i = beg + lane; i < end; i += 32)
        g_alpha[i] *= inv;
}

// ---------------- aggregation: block (128 thr) per dst node -----------------
__global__ void aggregate_kernel(const float* __restrict__ xl, const float* __restrict__ sk,
                                 const float* __restrict__ bc, const float* __restrict__ bs,
                                 float* __restrict__ out, int D, int doRelu) {
    int v = blockIdx.x;
    int tid = threadIdx.x;
    int beg = g_rowptr[v], end = g_rowptr[v + 1];
    __shared__ int   s_src[128];
    __shared__ float s_a[128];

    int npt = D >> 7;
    float acc[4] = {0.f, 0.f, 0.f, 0.f};

    for (int c = beg; c < end; c += 128) {
        int m = min(128, end - c);
        if (tid < m) {
            s_src[tid] = g_srcs[c + tid];
            s_a[tid]   = g_alpha[c + tid];
        }
        __syncthreads();
        for (int j = 0; j < m; j++) {
            const float* row = xl + (size_t)s_src[j] * D;
            float a = s_a[j];
#pragma unroll
            for (int t = 0; t < 4; t++)
                if (t < npt) acc[t] = fmaf(a, row[tid + t * 128], acc[t]);
        }
        __syncthreads();
    }

#pragma unroll
    for (int t = 0; t < 4; t++) {
        if (t < npt) {
            int d = tid + t * 128;
            float o = acc[t] + bc[d] + bs[d] + sk[(size_t)v * D + d];
            if (doRelu) o = fmaxf(o, 0.f);
            out[(size_t)v * D + d] = o;
        }
    }
}

// ---------------- host-side orchestration -----------------------------------
static void run_layer(const float* A, int K, int D,
                      const float* Wl, const float* Wr, const float* Ws,
                      const float* att, const float* bc, const float* bs,
                      float* out, int doRelu,
                      float* xl, float* xr, float* sk,
                      const int* src, const int* dst) {
    dim3 gg(D / BN, (N_NODES + BM - 1) / BM);
    gemm_tf32_kernel<<<gg, 256>>>(A, Wl, xl, N_NODES, D, K);
    gemm_tf32_kernel<<<gg, 256>>>(A, Wr, xr, N_NODES, D, K);
    gemm_tf32_kernel<<<gg, 256>>>(A, Ws, sk, N_NODES, D, K);

    int warpsPerBlock = 8;
    int nb = (N_EDGES + warpsPerBlock - 1) / warpsPerBlock;
    scores_kernel<<<nb, warpsPerBlock * 32>>>(xl, xr, att, src, dst, D);

    int nbv = (N_NODES + warpsPerBlock - 1) / warpsPerBlock;
    softmax_kernel<<<nbv, warpsPerBlock * 32>>>();

    aggregate_kernel<<<N_NODES, 128>>>(xl, sk, bc, bs, out, D, doRelu);
}

extern "C" void kernel_launch(void* const* d_in, const int* in_sizes, int n_in,
                              void* d_out, int out_size) {
    const float* x  = (const float*)d_in[0];
    const int*   ei = (const int*)d_in[1];
    const int* src = ei;
    const int* dst = ei + N_EDGES;

    const float* Wl[3]  = {(const float*)d_in[2],  (const float*)d_in[8],  (const float*)d_in[14]};
    const float* Wr[3]  = {(const float*)d_in[3],  (const float*)d_in[9],  (const float*)d_in[15]};
    const float* att[3] = {(const float*)d_in[4],  (const float*)d_in[10], (const float*)d_in[16]};
    const float* bc[3]  = {(const float*)d_in[5],  (const float*)d_in[11], (const float*)d_in[17]};
    const float* Ws[3]  = {(const float*)d_in[6],  (const float*)d_in[12], (const float*)d_in[18]};
    const float* bs[3]  = {(const float*)d_in[7],  (const float*)d_in[13], (const float*)d_in[19]};

    float *xl, *xr, *sk, *h1, *h2;
    cudaGetSymbolAddress((void**)&xl, g_xl);
    cudaGetSymbolAddress((void**)&xr, g_xr);
    cudaGetSymbolAddress((void**)&sk, g_sk);
    cudaGetSymbolAddress((void**)&h1, g_h1);
    cudaGetSymbolAddress((void**)&h2, g_h2);

    // CSR build (counting sort of edges by dst)
    zero_counts_kernel<<<(N_NODES + 255) / 256, 256>>>();
    hist_kernel<<<(N_EDGES + 255) / 256, 256>>>(dst);
    scan_kernel<<<1, 256>>>();
    scatter_kernel<<<(N_EDGES + 255) / 256, 256>>>(src, dst);

    // Layer 1: 256 -> 512, relu
    run_layer(x,  256, 512, Wl[0], Wr[0], Ws[0], att[0], bc[0], bs[0], h1, 1, xl, xr, sk, src, dst);
    // Layer 2: 512 -> 256, relu
    run_layer(h1, 512, 256, Wl[1], Wr[1], Ws[1], att[1], bc[1], bs[1], h2, 1, xl, xr, sk, src, dst);
    // Layer 3: 256 -> 128, no relu
    run_layer(h2, 256, 128, Wl[2], Wr[2], Ws[2], att[2], bc[2], bs[2], (float*)d_out, 0, xl, xr, sk, src, dst);
}

// round 5
// speedup vs baseline: 2.4189x; 1.2870x over previous
#include <cuda_runtime.h>
#include <cstdint>
#include <stdint.h>
#include <math.h>

#define N_NODES 20000
#define N_EDGES 320000
#define DMAX    512

// ---------------- scratch (static device globals; no allocation allowed) ----
__device__ __align__(16) float g_xl[N_NODES * DMAX];
__device__ __align__(16) float g_xr[N_NODES * DMAX];
__device__ __align__(16) float g_sk[N_NODES * DMAX];
__device__ __align__(16) float g_h1[N_NODES * 512];
__device__ __align__(16) float g_h2[N_NODES * 256];
__device__ float g_alpha[N_EDGES];
__device__ int   g_srcs [N_EDGES];
__device__ int   g_count [N_NODES];
__device__ int   g_cursor[N_NODES];
__device__ int   g_rowptr[N_NODES + 1];

// ---------------- CSR build (counting sort by dst) --------------------------
__global__ void zero_counts_kernel() {
    int i = blockIdx.x * blockDim.x + threadIdx.x;
    if (i < N_NODES) { g_count[i] = 0; g_cursor[i] = 0; }
}

__global__ void hist_kernel(const int* __restrict__ dst) {
    int e = blockIdx.x * blockDim.x + threadIdx.x;
    if (e < N_EDGES) atomicAdd(&g_count[dst[e]], 1);
}

__global__ void scan_kernel() {
    __shared__ int part[256];
    const int n = N_NODES;
    int tid = threadIdx.x;
    int chunk = (n + 255) / 256;
    int beg = tid * chunk;
    int end = min(beg + chunk, n);
    int sum = 0;
    for (int i = beg; i < end; i++) sum += g_count[i];
    part[tid] = sum;
    __syncthreads();
    for (int off = 1; off < 256; off <<= 1) {
        int v = (tid >= off) ? part[tid - off] : 0;
        __syncthreads();
        part[tid] += v;
        __syncthreads();
    }
    int run = (tid > 0) ? part[tid - 1] : 0;
    for (int i = beg; i < end; i++) {
        int c = g_count[i];
        g_rowptr[i] = run;
        run += c;
    }
    if (tid == 255) g_rowptr[n] = run;
}

__global__ void scatter_kernel(const int* __restrict__ src, const int* __restrict__ dst) {
    int e = blockIdx.x * blockDim.x + threadIdx.x;
    if (e < N_EDGES) {
        int d = dst[e];
        int pos = g_rowptr[d] + atomicAdd(&g_cursor[d], 1);
        g_srcs[pos] = src[e];
    }
}

// ---------------- TF32 tensor-core GEMM (z-batched over 3 weight mats) ------
// CTA tile 128x128x16, 8 warps (4m x 2n), warp tile 32x64, mma.m16n8k8 tf32.
// 2-stage cp.async pipeline. Requires K%16==0, N%128==0.
#define BM 128
#define BN 128
#define BK 16
#define AP (BK + 4)
#define BP (BN + 8)

__device__ __forceinline__ uint32_t f2tf32(float x) {
    uint32_t r;
    asm("cvt.rna.tf32.f32 %0, %1;" : "=r"(r) : "f"(x));
    return r;
}

__device__ __forceinline__ void cpasync16(void* smem, const void* g, int sz) {
    uint32_t sa = (uint32_t)__cvta_generic_to_shared(smem);
    asm volatile("cp.async.cg.shared.global [%0], [%1], 16, %2;\n"
                 :: "r"(sa), "l"(g), "r"(sz));
}

__global__ __launch_bounds__(256, 2)
void gemm_tf32_b3_kernel(const float* __restrict__ A,
                         const float* __restrict__ B0, const float* __restrict__ B1,
                         const float* __restrict__ B2,
                         float* __restrict__ C0, float* __restrict__ C1,
                         float* __restrict__ C2,
                         int M, int N, int K) {
    const float* B = (blockIdx.z == 0) ? B0 : (blockIdx.z == 1) ? B1 : B2;
    float*       C = (blockIdx.z == 0) ? C0 : (blockIdx.z == 1) ? C1 : C2;

    __shared__ float As[2][BM][AP];
    __shared__ float Bs[2][BK][BP];

    int tid  = threadIdx.x;
    int warp = tid >> 5;
    int lane = tid & 31;
    int blockRow = blockIdx.y * BM;
    int blockCol = blockIdx.x * BN;
    int wm = (warp >> 1) * 32;
    int wn = (warp & 1) * 64;

    float acc[2][8][4];
#pragma unroll
    for (int i = 0; i < 2; i++)
#pragma unroll
        for (int j = 0; j < 8; j++)
#pragma unroll
            for (int t = 0; t < 4; t++) acc[i][j][t] = 0.f;

    auto loadStage = [&](int s, int k0) {
#pragma unroll
        for (int j = 0; j < 2; j++) {
            int c = tid + j * 256;
            int row = c >> 2;
            int col = (c & 3) * 4;
            int gRow = blockRow + row;
            int ok = (gRow < M);
            const float* gp = A + (size_t)(ok ? gRow : 0) * K + k0 + col;
            cpasync16(&As[s][row][col], gp, ok ? 16 : 0);
        }
#pragma unroll
        for (int j = 0; j < 2; j++) {
            int c = tid + j * 256;
            int k = c >> 5;
            int col = (c & 31) * 4;
            const float* gp = B + (size_t)(k0 + k) * N + blockCol + col;
            cpasync16(&Bs[s][k][col], gp, 16);
        }
        asm volatile("cp.async.commit_group;\n");
    };

    int nK = K / BK;
    loadStage(0, 0);

    for (int kt = 0; kt < nK; kt++) {
        int s = kt & 1;
        if (kt + 1 < nK) {
            loadStage(s ^ 1, (kt + 1) * BK);
            asm volatile("cp.async.wait_group 1;\n");
        } else {
            asm volatile("cp.async.wait_group 0;\n");
        }
        __syncthreads();

#pragma unroll
        for (int ks = 0; ks < 2; ks++) {
            int kb = ks * 8;
            uint32_t aF[2][4];
#pragma unroll
            for (int i = 0; i < 2; i++) {
                int r0 = wm + i * 16 + (lane >> 2);
                int c0 = kb + (lane & 3);
                aF[i][0] = f2tf32(As[s][r0][c0]);
                aF[i][1] = f2tf32(As[s][r0 + 8][c0]);
                aF[i][2] = f2tf32(As[s][r0][c0 + 4]);
                aF[i][3] = f2tf32(As[s][r0 + 8][c0 + 4]);
            }
            uint32_t bF[8][2];
#pragma unroll
            for (int j = 0; j < 8; j++) {
                int kr = kb + (lane & 3);
                int nc = wn + j * 8 + (lane >> 2);
                bF[j][0] = f2tf32(Bs[s][kr][nc]);
                bF[j][1] = f2tf32(Bs[s][kr + 4][nc]);
            }
#pragma unroll
            for (int i = 0; i < 2; i++)
#pragma unroll
                for (int j = 0; j < 8; j++) {
                    asm volatile(
                        "mma.sync.aligned.m16n8k8.row.col.f32.tf32.tf32.f32 "
                        "{%0,%1,%2,%3}, {%4,%5,%6,%7}, {%8,%9}, {%0,%1,%2,%3};\n"
                        : "+f"(acc[i][j][0]), "+f"(acc[i][j][1]),
                          "+f"(acc[i][j][2]), "+f"(acc[i][j][3])
                        : "r"(aF[i][0]), "r"(aF[i][1]), "r"(aF[i][2]), "r"(aF[i][3]),
                          "r"(bF[j][0]), "r"(bF[j][1]));
                }
        }
        __syncthreads();
    }

#pragma unroll
    for (int i = 0; i < 2; i++) {
#pragma unroll
        for (int j = 0; j < 8; j++) {
            int r0 = blockRow + wm + i * 16 + (lane >> 2);
            int c0 = blockCol + wn + j * 8 + (lane & 3) * 2;
            if (r0 < M) {
                float2 v = make_float2(acc[i][j][0], acc[i][j][1]);
                *(float2*)(C + (size_t)r0 * N + c0) = v;
            }
            if (r0 + 8 < M) {
                float2 v = make_float2(acc[i][j][2], acc[i][j][3]);
                *(float2*)(C + (size_t)(r0 + 8) * N + c0) = v;
            }
        }
    }
}

// ---------------- fused score + segment softmax: warp per dst node ----------
// Warp holds xr[v] and att in registers; streams xl[src] rows (CSR order).
// Scores staged in g_alpha with chunk-aligned lane slots: every g_alpha element
// is written and re-read by the SAME thread (no cross-thread visibility issue).
__global__ void score_softmax_kernel(const float* __restrict__ xl,
                                     const float* __restrict__ xr,
                                     const float* __restrict__ att, int D) {
    int v = (blockIdx.x * blockDim.x + threadIdx.x) >> 5;
    if (v >= N_NODES) return;
    int lane = threadIdx.x & 31;
    int beg = g_rowptr[v], end = g_rowptr[v + 1];
    if (beg == end) return;

    int nk4 = D >> 7;  // float4 chunks per lane: 4 (D=512), 2, 1
    const float4* xr4  = (const float4*)(xr + (size_t)v * D);
    const float4* att4 = (const float4*)att;
    float4 xrv[4], atv[4];
#pragma unroll
    for (int k = 0; k < 4; k++)
        if (k < nk4) { xrv[k] = xr4[lane + 32 * k]; atv[k] = att4[lane + 32 * k]; }

    float m = -INFINITY;
    // pass 1: sequential over edges, whole warp per edge
    for (int c = beg; c < end; c += 32) {
        int cend = min(c + 32, end);
        float my = 0.f;
        for (int i = c; i < cend; i++) {
            int s = g_srcs[i];   // uniform across warp (broadcast)
            const float4* xs = (const float4*)(xl + (size_t)s * D);
            float acc = 0.f;
#pragma unroll
            for (int k = 0; k < 4; k++) {
                if (k < nk4) {
                    float4 vx = xs[lane + 32 * k];
                    float t;
                    t = vx.x + xrv[k].x; acc = fmaf((t > 0.f ? t : 0.2f * t), atv[k].x, acc);
                    t = vx.y + xrv[k].y; acc = fmaf((t > 0.f ? t : 0.2f * t), atv[k].y, acc);
                    t = vx.z + xrv[k].z; acc = fmaf((t > 0.f ? t : 0.2f * t), atv[k].z, acc);
                    t = vx.w + xrv[k].w; acc = fmaf((t > 0.f ? t : 0.2f * t), atv[k].w, acc);
                }
            }
#pragma unroll
            for (int off = 16; off > 0; off >>= 1)
                acc += __shfl_xor_sync(0xFFFFFFFFu, acc, off);
            m = fmaxf(m, acc);          // all lanes hold full score
            if (lane == i - c) my = acc; // this lane owns slot i
        }
        if (c + lane < cend) g_alpha[c + lane] = my;  // coalesced, same-thread reread below
    }

    // pass 2: exp & normalize (same lane slots as pass 1)
    float ssum = 0.f;
    for (int i = beg + lane; i < end; i += 32) {
        float ex = __expf(g_alpha[i] - m);
        g_alpha[i] = ex;
        ssum += ex;
    }
#pragma unroll
    for (int off = 16; off > 0; off >>= 1)
        ssum += __shfl_xor_sync(0xFFFFFFFFu, ssum, off);
    float inv = 1.f / (ssum + 1e-16f);
    for (int i = beg + lane; i < end; i += 32)
        g_alpha[i] *= inv;
}

// ---------------- aggregation: block (D/4 threads) per dst node, float4 -----
__global__ void aggregate_kernel(const float* __restrict__ xl, const float* __restrict__ sk,
                                 const float* __restrict__ bc, const float* __restrict__ bs,
                                 float* __restrict__ out, int D, int doRelu) {
    int v = blockIdx.x;
    int tid = threadIdx.x;
    int nthr = blockDim.x;          // == D/4
    int beg = g_rowptr[v], end = g_rowptr[v + 1];
    __shared__ int   s_src[128];
    __shared__ float s_a[128];

    float4 acc = make_float4(0.f, 0.f, 0.f, 0.f);

    for (int c = beg; c < end; c += nthr) {
        int mcnt = min(nthr, end - c);
        if (tid < mcnt) {
            s_src[tid] = g_srcs[c + tid];
            s_a[tid]   = g_alpha[c + tid];
        }
        __syncthreads();
        for (int j = 0; j < mcnt; j++) {
            const float4* row = (const float4*)(xl + (size_t)s_src[j] * D);
            float a = s_a[j];
            float4 vx = row[tid];
            acc.x = fmaf(a, vx.x, acc.x);
            acc.y = fmaf(a, vx.y, acc.y);
            acc.z = fmaf(a, vx.z, acc.z);
            acc.w = fmaf(a, vx.w, acc.w);
        }
        __syncthreads();
    }

    float4 vbc = ((const float4*)bc)[tid];
    float4 vbs = ((const float4*)bs)[tid];
    float4 vsk = ((const float4*)(sk + (size_t)v * D))[tid];
    float4 o;
    o.x = acc.x + vbc.x + vbs.x + vsk.x;
    o.y = acc.y + vbc.y + vbs.y + vsk.y;
    o.z = acc.z + vbc.z + vbs.z + vsk.z;
    o.w = acc.w + vbc.w + vbs.w + vsk.w;
    if (doRelu) {
        o.x = fmaxf(o.x, 0.f); o.y = fmaxf(o.y, 0.f);
        o.z = fmaxf(o.z, 0.f); o.w = fmaxf(o.w, 0.f);
    }
    ((float4*)(out + (size_t)v * D))[tid] = o;
}

// ---------------- host-side orchestration -----------------------------------
static void run_layer(const float* A, int K, int D,
                      const float* Wl, const float* Wr, const float* Ws,
                      const float* att, const float* bc, const float* bs,
                      float* out, int doRelu,
                      float* xl, float* xr, float* sk) {
    dim3 gg(D / BN, (N_NODES + BM - 1) / BM, 3);
    gemm_tf32_b3_kernel<<<gg, 256>>>(A, Wl, Wr, Ws, xl, xr, sk, N_NODES, D, K);

    int warpsPerBlock = 8;
    int nbv = (N_NODES + warpsPerBlock - 1) / warpsPerBlock;
    score_softmax_kernel<<<nbv, warpsPerBlock * 32>>>(xl, xr, att, D);

    aggregate_kernel<<<N_NODES, D / 4>>>(xl, sk, bc, bs, out, D, doRelu);
}

extern "C" void kernel_launch(void* const* d_in, const int* in_sizes, int n_in,
                              void* d_out, int out_size) {
    const float* x  = (const float*)d_in[0];
    const int*   ei = (const int*)d_in[1];
    const int* src = ei;
    const int* dst = ei + N_EDGES;

    const float* Wl[3]  = {(const float*)d_in[2],  (const float*)d_in[8],  (const float*)d_in[14]};
    const float* Wr[3]  = {(const float*)d_in[3],  (const float*)d_in[9],  (const float*)d_in[15]};
    const float* att[3] = {(const float*)d_in[4],  (const float*)d_in[10], (const float*)d_in[16]};
    const float* bc[3]  = {(const float*)d_in[5],  (const float*)d_in[11], (const float*)d_in[17]};
    const float* Ws[3]  = {(const float*)d_in[6],  (const float*)d_in[12], (const float*)d_in[18]};
    const float* bs[3]  = {(const float*)d_in[7],  (const float*)d_in[13], (const float*)d_in[19]};

    float *xl, *xr, *sk, *h1, *h2;
    cudaGetSymbolAddress((void**)&xl, g_xl);
    cudaGetSymbolAddress((void**)&xr, g_xr);
    cudaGetSymbolAddress((void**)&sk, g_sk);
    cudaGetSymbolAddress((void**)&h1, g_h1);
    cudaGetSymbolAddress((void**)&h2, g_h2);

    // CSR build (counting sort of edges by dst)
    zero_counts_kernel<<<(N_NODES + 255) / 256, 256>>>();
    hist_kernel<<<(N_EDGES + 255) / 256, 256>>>(dst);
    scan_kernel<<<1, 256>>>();
    scatter_kernel<<<(N_EDGES + 255) / 256, 256>>>(src, dst);

    // Layer 1: 256 -> 512, relu
    run_layer(x,  256, 512, Wl[0], Wr[0], Ws[0], att[0], bc[0], bs[0], h1, 1, xl, xr, sk);
    // Layer 2: 512 -> 256, relu
    run_layer(h1, 512, 256, Wl[1], Wr[1], Ws[1], att[1], bc[1], bs[1], h2, 1, xl, xr, sk);
    // Layer 3: 256 -> 128, no relu
    run_layer(h2, 256, 128, Wl[2], Wr[2], Ws[2], att[2], bc[2], bs[2], (float*)d_out, 0, xl, xr, sk);
}

// round 6
// speedup vs baseline: 3.0794x; 1.2731x over previous
#include <cuda_runtime.h>
#include <cstdint>
#include <stdint.h>
#include <math.h>

#define N_NODES 20000
#define N_EDGES 320000
#define DMAX    512

// ---------------- scratch (static device globals; no allocation allowed) ----
__device__ __align__(16) float g_xl[N_NODES * DMAX];
__device__ __align__(16) float g_xr[N_NODES * DMAX];
__device__ __align__(16) float g_sk[N_NODES * DMAX];
__device__ __align__(16) float g_h1[N_NODES * 512];   // tf32-rounded at write
__device__ __align__(16) float g_h2[N_NODES * 256];   // tf32-rounded at write
__device__ __align__(16) float g_xa[N_NODES * 256];   // tf32-rounded copy of x
__device__ __align__(16) float g_wt[900000];          // tf32-rounded weights (884736 used)
__device__ int   g_srcs [N_EDGES];
__device__ int   g_count [N_NODES];
__device__ int   g_cursor[N_NODES];
__device__ int   g_rowptr[N_NODES + 1];

__device__ __forceinline__ float tf32r(float x) {
    uint32_t r;
    asm("cvt.rna.tf32.f32 %0, %1;" : "=r"(r) : "f"(x));
    return __uint_as_float(r);
}

// ---------------- CSR build (counting sort by dst) --------------------------
__global__ void zero_counts_kernel() {
    int i = blockIdx.x * blockDim.x + threadIdx.x;
    if (i < N_NODES) { g_count[i] = 0; g_cursor[i] = 0; }
}

__global__ void hist_kernel(const int* __restrict__ dst) {
    int e = blockIdx.x * blockDim.x + threadIdx.x;
    if (e < N_EDGES) atomicAdd(&g_count[dst[e]], 1);
}

__global__ void scan_kernel() {
    __shared__ int part[256];
    const int n = N_NODES;
    int tid = threadIdx.x;
    int chunk = (n + 255) / 256;
    int beg = tid * chunk;
    int end = min(beg + chunk, n);
    int sum = 0;
    for (int i = beg; i < end; i++) sum += g_count[i];
    part[tid] = sum;
    __syncthreads();
    for (int off = 1; off < 256; off <<= 1) {
        int v = (tid >= off) ? part[tid - off] : 0;
        __syncthreads();
        part[tid] += v;
        __syncthreads();
    }
    int run = (tid > 0) ? part[tid - 1] : 0;
    for (int i = beg; i < end; i++) {
        int c = g_count[i];
        g_rowptr[i] = run;
        run += c;
    }
    if (tid == 255) g_rowptr[n] = run;
}

__global__ void scatter_kernel(const int* __restrict__ src, const int* __restrict__ dst) {
    int e = blockIdx.x * blockDim.x + threadIdx.x;
    if (e < N_EDGES) {
        int d = dst[e];
        int pos = g_rowptr[d] + atomicAdd(&g_cursor[d], 1);
        g_srcs[pos] = src[e];
    }
}

// ---------------- tf32 rounding prepass -------------------------------------
__global__ void round_copy_kernel(const float* __restrict__ in, float* __restrict__ out, int n4) {
    int i = blockIdx.x * blockDim.x + threadIdx.x;
    if (i < n4) {
        float4 v = ((const float4*)in)[i];
        v.x = tf32r(v.x); v.y = tf32r(v.y); v.z = tf32r(v.z); v.w = tf32r(v.w);
        ((float4*)out)[i] = v;
    }
}

struct WConv {
    const float* src[9];
    float*       dst[9];
    int          n4[9];
};

__global__ void round_weights_kernel(WConv wc) {
    int s = blockIdx.y;
    int i = blockIdx.x * blockDim.x + threadIdx.x;
    if (i < wc.n4[s]) {
        float4 v = ((const float4*)wc.src[s])[i];
        v.x = tf32r(v.x); v.y = tf32r(v.y); v.z = tf32r(v.z); v.w = tf32r(v.w);
        ((float4*)wc.dst[s])[i] = v;
    }
}

// ---------------- TF32 tensor-core GEMM (z-batched over 3 weight mats) ------
// Inputs are pre-rounded to tf32; fragments pass raw bits (no cvt in loop).
#define BM 128
#define BN 128
#define BK 16
#define AP (BK + 4)
#define BP (BN + 8)

__device__ __forceinline__ void cpasync16(void* smem, const void* g, int sz) {
    uint32_t sa = (uint32_t)__cvta_generic_to_shared(smem);
    asm volatile("cp.async.cg.shared.global [%0], [%1], 16, %2;\n"
                 :: "r"(sa), "l"(g), "r"(sz));
}

__global__ __launch_bounds__(256, 2)
void gemm_tf32_b3_kernel(const float* __restrict__ A,
                         const float* __restrict__ B0, const float* __restrict__ B1,
                         const float* __restrict__ B2,
                         float* __restrict__ C0, float* __restrict__ C1,
                         float* __restrict__ C2,
                         int M, int N, int K) {
    const float* B = (blockIdx.z == 0) ? B0 : (blockIdx.z == 1) ? B1 : B2;
    float*       C = (blockIdx.z == 0) ? C0 : (blockIdx.z == 1) ? C1 : C2;

    __shared__ float As[2][BM][AP];
    __shared__ float Bs[2][BK][BP];

    int tid  = threadIdx.x;
    int warp = tid >> 5;
    int lane = tid & 31;
    int blockRow = blockIdx.y * BM;
    int blockCol = blockIdx.x * BN;
    int wm = (warp >> 1) * 32;
    int wn = (warp & 1) * 64;

    float acc[2][8][4];
#pragma unroll
    for (int i = 0; i < 2; i++)
#pragma unroll
        for (int j = 0; j < 8; j++)
#pragma unroll
            for (int t = 0; t < 4; t++) acc[i][j][t] = 0.f;

    auto loadStage = [&](int s, int k0) {
#pragma unroll
        for (int j = 0; j < 2; j++) {
            int c = tid + j * 256;
            int row = c >> 2;
            int col = (c & 3) * 4;
            int gRow = blockRow + row;
            int ok = (gRow < M);
            const float* gp = A + (size_t)(ok ? gRow : 0) * K + k0 + col;
            cpasync16(&As[s][row][col], gp, ok ? 16 : 0);
        }
#pragma unroll
        for (int j = 0; j < 2; j++) {
            int c = tid + j * 256;
            int k = c >> 5;
            int col = (c & 31) * 4;
            const float* gp = B + (size_t)(k0 + k) * N + blockCol + col;
            cpasync16(&Bs[s][k][col], gp, 16);
        }
        asm volatile("cp.async.commit_group;\n");
    };

    int nK = K / BK;
    loadStage(0, 0);

    for (int kt = 0; kt < nK; kt++) {
        int s = kt & 1;
        if (kt + 1 < nK) {
            loadStage(s ^ 1, (kt + 1) * BK);
            asm volatile("cp.async.wait_group 1;\n");
        } else {
            asm volatile("cp.async.wait_group 0;\n");
        }
        __syncthreads();

#pragma unroll
        for (int ks = 0; ks < 2; ks++) {
            int kb = ks * 8;
            uint32_t aF[2][4];
#pragma unroll
            for (int i = 0; i < 2; i++) {
                int r0 = wm + i * 16 + (lane >> 2);
                int c0 = kb + (lane & 3);
                aF[i][0] = __float_as_uint(As[s][r0][c0]);
                aF[i][1] = __float_as_uint(As[s][r0 + 8][c0]);
                aF[i][2] = __float_as_uint(As[s][r0][c0 + 4]);
                aF[i][3] = __float_as_uint(As[s][r0 + 8][c0 + 4]);
            }
            uint32_t bF[8][2];
#pragma unroll
            for (int j = 0; j < 8; j++) {
                int kr = kb + (lane & 3);
                int nc = wn + j * 8 + (lane >> 2);
                bF[j][0] = __float_as_uint(Bs[s][kr][nc]);
                bF[j][1] = __float_as_uint(Bs[s][kr + 4][nc]);
            }
#pragma unroll
            for (int i = 0; i < 2; i++)
#pragma unroll
                for (int j = 0; j < 8; j++) {
                    asm volatile(
                        "mma.sync.aligned.m16n8k8.row.col.f32.tf32.tf32.f32 "
                        "{%0,%1,%2,%3}, {%4,%5,%6,%7}, {%8,%9}, {%0,%1,%2,%3};\n"
                        : "+f"(acc[i][j][0]), "+f"(acc[i][j][1]),
                          "+f"(acc[i][j][2]), "+f"(acc[i][j][3])
                        : "r"(aF[i][0]), "r"(aF[i][1]), "r"(aF[i][2]), "r"(aF[i][3]),
                          "r"(bF[j][0]), "r"(bF[j][1]));
                }
        }
        __syncthreads();
    }

#pragma unroll
    for (int i = 0; i < 2; i++) {
#pragma unroll
        for (int j = 0; j < 8; j++) {
            int r0 = blockRow + wm + i * 16 + (lane >> 2);
            int c0 = blockCol + wn + j * 8 + (lane & 3) * 2;
            if (r0 < M) {
                float2 v = make_float2(acc[i][j][0], acc[i][j][1]);
                *(float2*)(C + (size_t)r0 * N + c0) = v;
            }
            if (r0 + 8 < M) {
                float2 v = make_float2(acc[i][j][2], acc[i][j][3]);
                *(float2*)(C + (size_t)(r0 + 8) * N + c0) = v;
            }
        }
    }
}

// ---------------- fused edge phase: score + online softmax + aggregate ------
// Warp per dst node. xr[v], att in registers; each xl[src] row is read ONCE:
// used for the score and immediately accumulated with online-softmax rescaling.
// Epilogue adds bc + bs + skip, relu, optional tf32 rounding for next layer.
template <int NK4>   // float4 chunks per lane; D = NK4*128
__global__ void gat_edge_fused_kernel(const float* __restrict__ xl,
                                      const float* __restrict__ xr,
                                      const float* __restrict__ att,
                                      const float* __restrict__ sk,
                                      const float* __restrict__ bc,
                                      const float* __restrict__ bs,
                                      float* __restrict__ out,
                                      int doRelu, int roundOut) {
    const int D = NK4 * 128;
    int v = (blockIdx.x * blockDim.x + threadIdx.x) >> 5;
    if (v >= N_NODES) return;
    int lane = threadIdx.x & 31;
    int beg = g_rowptr[v], end = g_rowptr[v + 1];

    const float4* xr4  = (const float4*)(xr + (size_t)v * D);
    const float4* att4 = (const float4*)att;
    float4 xrv[NK4], atv[NK4], acc[NK4];
#pragma unroll
    for (int k = 0; k < NK4; k++) {
        xrv[k] = xr4[lane + 32 * k];
        atv[k] = att4[lane + 32 * k];
        acc[k] = make_float4(0.f, 0.f, 0.f, 0.f);
    }

    float m = -INFINITY, ssum = 0.f;
    for (int i = beg; i < end; i++) {
        int s = g_srcs[i];   // uniform across warp
        const float4* xs = (const float4*)(xl + (size_t)s * D);
        float4 vx[NK4];
#pragma unroll
        for (int k = 0; k < NK4; k++) vx[k] = xs[lane + 32 * k];

        float sc = 0.f;
#pragma unroll
        for (int k = 0; k < NK4; k++) {
            float t;
            t = vx[k].x + xrv[k].x; sc = fmaf((t > 0.f ? t : 0.2f * t), atv[k].x, sc);
            t = vx[k].y + xrv[k].y; sc = fmaf((t > 0.f ? t : 0.2f * t), atv[k].y, sc);
            t = vx[k].z + xrv[k].z; sc = fmaf((t > 0.f ? t : 0.2f * t), atv[k].z, sc);
            t = vx[k].w + xrv[k].w; sc = fmaf((t > 0.f ? t : 0.2f * t), atv[k].w, sc);
        }
#pragma unroll
        for (int off = 16; off > 0; off >>= 1)
            sc += __shfl_xor_sync(0xFFFFFFFFu, sc, off);

        float mn = fmaxf(m, sc);
        float scale = __expf(m - mn);   // first iter: exp(-inf)=0
        float w = __expf(sc - mn);
        ssum = ssum * scale + w;
#pragma unroll
        for (int k = 0; k < NK4; k++) {
            acc[k].x = fmaf(acc[k].x, scale, w * vx[k].x);
            acc[k].y = fmaf(acc[k].y, scale, w * vx[k].y);
            acc[k].z = fmaf(acc[k].z, scale, w * vx[k].z);
            acc[k].w = fmaf(acc[k].w, scale, w * vx[k].w);
        }
        m = mn;
    }

    float inv = 1.f / (ssum + 1e-16f);
    const float4* bc4 = (const float4*)bc;
    const float4* bs4 = (const float4*)bs;
    const float4* sk4 = (const float4*)(sk + (size_t)v * D);
    float4* out4 = (float4*)(out + (size_t)v * D);
#pragma unroll
    for (int k = 0; k < NK4; k++) {
        int idx = lane + 32 * k;
        float4 vbc = bc4[idx], vbs = bs4[idx], vsk = sk4[idx];
        float4 o;
        o.x = fmaf(acc[k].x, inv, vbc.x + vbs.x + vsk.x);
        o.y = fmaf(acc[k].y, inv, vbc.y + vbs.y + vsk.y);
        o.z = fmaf(acc[k].z, inv, vbc.z + vbs.z + vsk.z);
        o.w = fmaf(acc[k].w, inv, vbc.w + vbs.w + vsk.w);
        if (doRelu) {
            o.x = fmaxf(o.x, 0.f); o.y = fmaxf(o.y, 0.f);
            o.z = fmaxf(o.z, 0.f); o.w = fmaxf(o.w, 0.f);
        }
        if (roundOut) {
            o.x = tf32r(o.x); o.y = tf32r(o.y);
            o.z = tf32r(o.z); o.w = tf32r(o.w);
        }
        out4[idx] = o;
    }
}

// ---------------- host-side orchestration -----------------------------------
static void run_layer(const float* A, int K, int D,
                      const float* Wl, const float* Wr, const float* Ws,
                      const float* att, const float* bc, const float* bs,
                      float* out, int doRelu, int roundOut,
                      float* xl, float* xr, float* sk) {
    dim3 gg(D / BN, (N_NODES + BM - 1) / BM, 3);
    gemm_tf32_b3_kernel<<<gg, 256>>>(A, Wl, Wr, Ws, xl, xr, sk, N_NODES, D, K);

    int warpsPerBlock = 8;
    int nbv = (N_NODES + warpsPerBlock - 1) / warpsPerBlock;
    if (D == 512)
        gat_edge_fused_kernel<4><<<nbv, warpsPerBlock * 32>>>(xl, xr, att, sk, bc, bs, out, doRelu, roundOut);
    else if (D == 256)
        gat_edge_fused_kernel<2><<<nbv, warpsPerBlock * 32>>>(xl, xr, att, sk, bc, bs, out, doRelu, roundOut);
    else
        gat_edge_fused_kernel<1><<<nbv, warpsPerBlock * 32>>>(xl, xr, att, sk, bc, bs, out, doRelu, roundOut);
}

extern "C" void kernel_launch(void* const* d_in, const int* in_sizes, int n_in,
                              void* d_out, int out_size) {
    const float* x  = (const float*)d_in[0];
    const int*   ei = (const int*)d_in[1];
    const int* src = ei;
    const int* dst = ei + N_EDGES;

    const float* Wl[3]  = {(const float*)d_in[2],  (const float*)d_in[8],  (const float*)d_in[14]};
    const float* Wr[3]  = {(const float*)d_in[3],  (const float*)d_in[9],  (const float*)d_in[15]};
    const float* att[3] = {(const float*)d_in[4],  (const float*)d_in[10], (const float*)d_in[16]};
    const float* bc[3]  = {(const float*)d_in[5],  (const float*)d_in[11], (const float*)d_in[17]};
    const float* Ws[3]  = {(const float*)d_in[6],  (const float*)d_in[12], (const float*)d_in[18]};
    const float* bs[3]  = {(const float*)d_in[7],  (const float*)d_in[13], (const float*)d_in[19]};

    float *xl, *xr, *sk, *h1, *h2, *xa, *wt;
    cudaGetSymbolAddress((void**)&xl, g_xl);
    cudaGetSymbolAddress((void**)&xr, g_xr);
    cudaGetSymbolAddress((void**)&sk, g_sk);
    cudaGetSymbolAddress((void**)&h1, g_h1);
    cudaGetSymbolAddress((void**)&h2, g_h2);
    cudaGetSymbolAddress((void**)&xa, g_xa);
    cudaGetSymbolAddress((void**)&wt, g_wt);

    // tf32-rounded weight copies (layout: per-layer Wl, Wr, Ws)
    int wn[9]  = {256*512, 256*512, 256*512, 512*256, 512*256, 512*256, 256*128, 256*128, 256*128};
    const float* wsrc[9] = {Wl[0], Wr[0], Ws[0], Wl[1], Wr[1], Ws[1], Wl[2], Wr[2], Ws[2]};
    float* wdst[9];
    {
        int off = 0;
        for (int i = 0; i < 9; i++) { wdst[i] = wt + off; off += wn[i]; }
    }
    WConv wc;
    int maxn4 = 0;
    for (int i = 0; i < 9; i++) {
        wc.src[i] = wsrc[i];
        wc.dst[i] = wdst[i];
        wc.n4[i]  = wn[i] / 4;
        if (wc.n4[i] > maxn4) maxn4 = wc.n4[i];
    }
    dim3 wg((maxn4 + 255) / 256, 9);
    round_weights_kernel<<<wg, 256>>>(wc);

    // tf32-rounded input x
    round_copy_kernel<<<(N_NODES * 256 / 4 + 255) / 256, 256>>>(x, xa, N_NODES * 256 / 4);

    // CSR build (counting sort of edges by dst)
    zero_counts_kernel<<<(N_NODES + 255) / 256, 256>>>();
    hist_kernel<<<(N_EDGES + 255) / 256, 256>>>(dst);
    scan_kernel<<<1, 256>>>();
    scatter_kernel<<<(N_EDGES + 255) / 256, 256>>>(src, dst);

    // Layer 1: 256 -> 512, relu, round for next GEMM
    run_layer(xa, 256, 512, wdst[0], wdst[1], wdst[2], att[0], bc[0], bs[0], h1, 1, 1, xl, xr, sk);
    // Layer 2: 512 -> 256, relu, round for next GEMM
    run_layer(h1, 512, 256, wdst[3], wdst[4], wdst[5], att[1], bc[1], bs[1], h2, 1, 1, xl, xr, sk);
    // Layer 3: 256 -> 128, no relu, full fp32 output
    run_layer(h2, 256, 128, wdst[6], wdst[7], wdst[8], att[2], bc[2], bs[2], (float*)d_out, 0, 0, xl, xr, sk);
}